// round 2
// baseline (speedup 1.0000x reference)
#include <cuda_runtime.h>
#include <math.h>

#define D_MODEL 1024
#define NHEAD 16
#define HEAD_DIM 64
#define HIDDEN 4096
#define BATCH 2
#define SEQ 2048
#define ROWS (BATCH * SEQ)   // 4096

// ---------------- scratch (allocation-free: __device__ globals) ----------------
__device__ float g_xn [ROWS * D_MODEL];        // 16.8 MB
__device__ float g_qkv[ROWS * 3 * D_MODEL];    // 50 MB
__device__ float g_att[ROWS * D_MODEL];        // 16.8 MB
__device__ float g_x1 [ROWS * D_MODEL];        // 16.8 MB
__device__ float g_h  [ROWS * 2 * HIDDEN];     // 134 MB
__device__ float g_ffn[ROWS * HIDDEN];         // 67 MB

// ---------------- RMSNorm: one block per row ----------------
__global__ __launch_bounds__(256) void rmsnorm_kernel(
    const float* __restrict__ x, const float* __restrict__ scale,
    float* __restrict__ y)
{
    int row = blockIdx.x;
    const float* xr = x + (size_t)row * D_MODEL;
    float*       yr = y + (size_t)row * D_MODEL;
    int t = threadIdx.x;
    float v0 = xr[t], v1 = xr[t + 256], v2 = xr[t + 512], v3 = xr[t + 768];
    float ss = v0*v0 + v1*v1 + v2*v2 + v3*v3;
    #pragma unroll
    for (int o = 16; o; o >>= 1) ss += __shfl_xor_sync(0xffffffffu, ss, o);
    __shared__ float red[8];
    if ((t & 31) == 0) red[t >> 5] = ss;
    __syncthreads();
    float tot = 0.f;
    #pragma unroll
    for (int w = 0; w < 8; w++) tot += red[w];
    float r = rsqrtf(tot * (1.0f / D_MODEL) + 1e-8f);
    yr[t]       = scale[t]       * v0 * r;
    yr[t + 256] = scale[t + 256] * v1 * r;
    yr[t + 512] = scale[t + 512] * v2 * r;
    yr[t + 768] = scale[t + 768] * v3 * r;
}

// ---------------- Generic SGEMM: C = A[M,K] @ B[K,N] + bias (+ res) ----------------
// 128x128 tile, BK=16, 256 threads, 8x8 micro-tile per thread.
__global__ __launch_bounds__(256) void sgemm_kernel(
    const float* __restrict__ A, const float* __restrict__ Bm,
    const float* __restrict__ bias, const float* __restrict__ res,
    float* __restrict__ C, int M, int N, int K)
{
    __shared__ float As[16][128];
    __shared__ float Bs[16][128];
    int tid = threadIdx.x;
    int bn = blockIdx.x, bm = blockIdx.y;
    int tr = (tid >> 4) << 3;    // 0..120
    int tc = (tid & 15) << 3;    // 0..120

    float acc[8][8];
    #pragma unroll
    for (int i = 0; i < 8; i++)
        #pragma unroll
        for (int j = 0; j < 8; j++) acc[i][j] = 0.f;

    for (int k0 = 0; k0 < K; k0 += 16) {
        #pragma unroll
        for (int t = 0; t < 2; t++) {
            int f  = tid * 2 + t;
            // A tile 128x16 -> As transposed [k][m]
            int ra = f >> 2, ca = (f & 3) << 2;
            float4 va = *reinterpret_cast<const float4*>(
                A + (size_t)(bm * 128 + ra) * K + k0 + ca);
            As[ca + 0][ra] = va.x; As[ca + 1][ra] = va.y;
            As[ca + 2][ra] = va.z; As[ca + 3][ra] = va.w;
            // B tile 16x128 direct
            int rb = f >> 5, cb = (f & 31) << 2;
            *reinterpret_cast<float4*>(&Bs[rb][cb]) =
                *reinterpret_cast<const float4*>(
                    Bm + (size_t)(k0 + rb) * N + bn * 128 + cb);
        }
        __syncthreads();
        #pragma unroll
        for (int kk = 0; kk < 16; kk++) {
            float a[8], b[8];
            #pragma unroll
            for (int i = 0; i < 8; i++) a[i] = As[kk][tr + i];
            #pragma unroll
            for (int j = 0; j < 8; j++) b[j] = Bs[kk][tc + j];
            #pragma unroll
            for (int i = 0; i < 8; i++)
                #pragma unroll
                for (int j = 0; j < 8; j++)
                    acc[i][j] = fmaf(a[i], b[j], acc[i][j]);
        }
        __syncthreads();
    }

    int col0 = bn * 128 + tc;
    const float4 bv0 = *reinterpret_cast<const float4*>(bias + col0);
    const float4 bv1 = *reinterpret_cast<const float4*>(bias + col0 + 4);
    #pragma unroll
    for (int i = 0; i < 8; i++) {
        size_t off = (size_t)(bm * 128 + tr + i) * N + col0;
        float4 o0, o1;
        o0.x = acc[i][0] + bv0.x; o0.y = acc[i][1] + bv0.y;
        o0.z = acc[i][2] + bv0.z; o0.w = acc[i][3] + bv0.w;
        o1.x = acc[i][4] + bv1.x; o1.y = acc[i][5] + bv1.y;
        o1.z = acc[i][6] + bv1.z; o1.w = acc[i][7] + bv1.w;
        if (res) {
            float4 r0 = *reinterpret_cast<const float4*>(res + off);
            float4 r1 = *reinterpret_cast<const float4*>(res + off + 4);
            o0.x += r0.x; o0.y += r0.y; o0.z += r0.z; o0.w += r0.w;
            o1.x += r1.x; o1.y += r1.y; o1.z += r1.z; o1.w += r1.w;
        }
        *reinterpret_cast<float4*>(C + off)     = o0;
        *reinterpret_cast<float4*>(C + off + 4) = o1;
    }
}

// ---------------- Flash attention (causal + analytic ALiBi) ----------------
// grid = (SEQ/64, BATCH*NHEAD), 256 threads. 64x64 Q/K/V tiles.
#define FST 65       // smem row stride (floats)
#define NEG_INF -1e30f
#define INV_SQRT_DH 0.125f

__global__ __launch_bounds__(256) void flash_attn_kernel(
    const float* __restrict__ qkv, float* __restrict__ out)
{
    extern __shared__ float sm[];
    float* Qs = sm;
    float* Ks = sm + 64 * FST;
    float* Vs = sm + 2 * 64 * FST;
    float* Ps = sm + 3 * 64 * FST;

    int qt = blockIdx.x;
    int bh = blockIdx.y;
    int b  = bh >> 4, h = bh & 15;
    float slope = exp2f(-0.5f * (float)(h + 1));

    int tid = threadIdx.x;
    int tm = tid >> 4, tn = tid & 15;
    int r0 = tm << 2, c0 = tn << 2;

    // load Q tile
    {
        int r  = tid >> 2;
        int cl = (tid & 3) << 4;
        const float* src = qkv + (size_t)(b * SEQ + qt * 64 + r) * 3072 + h * 64 + cl;
        float* dst = Qs + r * FST + cl;
        #pragma unroll
        for (int t = 0; t < 4; t++) {
            float4 v = *reinterpret_cast<const float4*>(src + t * 4);
            dst[t*4+0] = v.x; dst[t*4+1] = v.y; dst[t*4+2] = v.z; dst[t*4+3] = v.w;
        }
    }

    float m_i[4], l_i[4], o[4][4];
    #pragma unroll
    for (int i = 0; i < 4; i++) {
        m_i[i] = NEG_INF; l_i[i] = 0.f;
        #pragma unroll
        for (int j = 0; j < 4; j++) o[i][j] = 0.f;
    }

    for (int kt = 0; kt <= qt; kt++) {
        // load K, V tiles
        {
            int r  = tid >> 2;
            int cl = (tid & 3) << 4;
            const float* srck = qkv + (size_t)(b * SEQ + kt * 64 + r) * 3072 + 1024 + h * 64 + cl;
            const float* srcv = srck + 1024;
            float* dk = Ks + r * FST + cl;
            float* dv = Vs + r * FST + cl;
            #pragma unroll
            for (int t = 0; t < 4; t++) {
                float4 vk = *reinterpret_cast<const float4*>(srck + t * 4);
                float4 vv = *reinterpret_cast<const float4*>(srcv + t * 4);
                dk[t*4+0] = vk.x; dk[t*4+1] = vk.y; dk[t*4+2] = vk.z; dk[t*4+3] = vk.w;
                dv[t*4+0] = vv.x; dv[t*4+1] = vv.y; dv[t*4+2] = vv.z; dv[t*4+3] = vv.w;
            }
        }
        __syncthreads();

        // S = Q @ K^T
        float s[4][4];
        #pragma unroll
        for (int i = 0; i < 4; i++)
            #pragma unroll
            for (int j = 0; j < 4; j++) s[i][j] = 0.f;
        #pragma unroll 8
        for (int d = 0; d < 64; d++) {
            float qv[4], kv[4];
            #pragma unroll
            for (int i = 0; i < 4; i++) qv[i] = Qs[(r0 + i) * FST + d];
            #pragma unroll
            for (int j = 0; j < 4; j++) kv[j] = Ks[(c0 + j) * FST + d];
            #pragma unroll
            for (int i = 0; i < 4; i++)
                #pragma unroll
                for (int j = 0; j < 4; j++)
                    s[i][j] = fmaf(qv[i], kv[j], s[i][j]);
        }

        int ibase = qt * 64 + r0, jbase = kt * 64 + c0;
        #pragma unroll
        for (int i = 0; i < 4; i++) {
            int ii = ibase + i;
            float rmax = NEG_INF;
            #pragma unroll
            for (int j = 0; j < 4; j++) {
                int jj = jbase + j;
                float val = s[i][j] * INV_SQRT_DH - slope * (float)(ii - jj);
                if (jj > ii) val = NEG_INF;
                s[i][j] = val;
                rmax = fmaxf(rmax, val);
            }
            #pragma unroll
            for (int off = 8; off; off >>= 1)
                rmax = fmaxf(rmax, __shfl_xor_sync(0xffffffffu, rmax, off, 16));
            float mnew = fmaxf(m_i[i], rmax);
            float corr = __expf(m_i[i] - mnew);
            m_i[i] = mnew;
            float psum = 0.f;
            #pragma unroll
            for (int j = 0; j < 4; j++) {
                float p = __expf(s[i][j] - mnew);
                s[i][j] = p;
                psum += p;
            }
            #pragma unroll
            for (int off = 8; off; off >>= 1)
                psum += __shfl_xor_sync(0xffffffffu, psum, off, 16);
            l_i[i] = l_i[i] * corr + psum;
            #pragma unroll
            for (int j = 0; j < 4; j++) {
                o[i][j] *= corr;
                Ps[(r0 + i) * FST + c0 + j] = s[i][j];
            }
        }
        __syncthreads();

        // O += P @ V
        #pragma unroll 8
        for (int c = 0; c < 64; c++) {
            float pv[4], vv[4];
            #pragma unroll
            for (int i = 0; i < 4; i++) pv[i] = Ps[(r0 + i) * FST + c];
            #pragma unroll
            for (int j = 0; j < 4; j++) vv[j] = Vs[c * FST + c0 + j];
            #pragma unroll
            for (int i = 0; i < 4; i++)
                #pragma unroll
                for (int j = 0; j < 4; j++)
                    o[i][j] = fmaf(pv[i], vv[j], o[i][j]);
        }
        __syncthreads();  // before next tile overwrites K/V/P
    }

    #pragma unroll
    for (int i = 0; i < 4; i++) {
        float inv = 1.0f / l_i[i];
        size_t off = (size_t)(b * SEQ + qt * 64 + r0 + i) * D_MODEL + h * 64 + c0;
        float4 ov;
        ov.x = o[i][0] * inv; ov.y = o[i][1] * inv;
        ov.z = o[i][2] * inv; ov.w = o[i][3] * inv;
        *reinterpret_cast<float4*>(out + off) = ov;
    }
}

// ---------------- SwiGLU: g = silu(h[:,H:]) * h[:,:H] ----------------
__global__ __launch_bounds__(256) void swiglu_kernel(
    const float* __restrict__ h, float* __restrict__ g)
{
    int idx = blockIdx.x * 256 + threadIdx.x;   // over ROWS*HIDDEN
    int r = idx >> 12;          // / 4096
    int j = idx & 4095;
    const float* hr = h + (size_t)r * (2 * HIDDEN);
    float xp = hr[j];
    float gt = hr[j + HIDDEN];
    float sg = 1.0f / (1.0f + __expf(-gt));
    g[idx] = gt * sg * xp;
}

// ---------------- launch ----------------
extern "C" void kernel_launch(void* const* d_in, const int* in_sizes, int n_in,
                              void* d_out, int out_size)
{
    const float* x      = (const float*)d_in[0];
    // d_in[1] attn_mask, d_in[2] alibi_bias: computed analytically on device
    const float* w_qkv  = (const float*)d_in[3];
    const float* b_qkv  = (const float*)d_in[4];
    const float* w_o    = (const float*)d_in[5];
    const float* b_o    = (const float*)d_in[6];
    const float* scale1 = (const float*)d_in[7];
    const float* scale2 = (const float*)d_in[8];
    const float* w1     = (const float*)d_in[9];
    const float* b1     = (const float*)d_in[10];
    const float* w2     = (const float*)d_in[11];
    const float* b2     = (const float*)d_in[12];
    float* out = (float*)d_out;

    float *xn, *qkvp, *att, *x1, *hbuf, *ffn;
    cudaGetSymbolAddress((void**)&xn,   g_xn);
    cudaGetSymbolAddress((void**)&qkvp, g_qkv);
    cudaGetSymbolAddress((void**)&att,  g_att);
    cudaGetSymbolAddress((void**)&x1,   g_x1);
    cudaGetSymbolAddress((void**)&hbuf, g_h);
    cudaGetSymbolAddress((void**)&ffn,  g_ffn);

    int smem = 4 * 64 * FST * (int)sizeof(float);  // 66560 B
    cudaFuncSetAttribute(flash_attn_kernel,
                         cudaFuncAttributeMaxDynamicSharedMemorySize, smem);

    // 1) xn = rmsnorm(x, scale1)
    rmsnorm_kernel<<<ROWS, 256>>>(x, scale1, xn);
    // 2) qkv = xn @ w_qkv + b_qkv
    sgemm_kernel<<<dim3(3 * D_MODEL / 128, ROWS / 128), 256>>>(
        xn, w_qkv, b_qkv, nullptr, qkvp, ROWS, 3 * D_MODEL, D_MODEL);
    // 3) att = flash_attention(q, k, v) with causal + alibi
    flash_attn_kernel<<<dim3(SEQ / 64, BATCH * NHEAD), 256, smem>>>(qkvp, att);
    // 4) x1 = x + att @ w_o + b_o
    sgemm_kernel<<<dim3(D_MODEL / 128, ROWS / 128), 256>>>(
        att, w_o, b_o, x, x1, ROWS, D_MODEL, D_MODEL);
    // 5) xn = rmsnorm(x1, scale2)
    rmsnorm_kernel<<<ROWS, 256>>>(x1, scale2, xn);
    // 6) h = xn @ w1 + b1
    sgemm_kernel<<<dim3(2 * HIDDEN / 128, ROWS / 128), 256>>>(
        xn, w1, b1, nullptr, hbuf, ROWS, 2 * HIDDEN, D_MODEL);
    // 7) ffn = silu(gate) * x_proj
    swiglu_kernel<<<ROWS * HIDDEN / 256, 256>>>(hbuf, ffn);
    // 8) out = x1 + ffn @ w2 + b2
    sgemm_kernel<<<dim3(D_MODEL / 128, ROWS / 128), 256>>>(
        ffn, w2, b2, x1, out, ROWS, D_MODEL, HIDDEN);
}

// round 7
// speedup vs baseline: 1.5365x; 1.5365x over previous
#include <cuda_runtime.h>
#include <cuda_bf16.h>
#include <mma.h>
#include <math.h>
#include <stdint.h>

using namespace nvcuda;

#define D_MODEL 1024
#define NHEAD 16
#define HEAD_DIM 64
#define HIDDEN 4096
#define BATCH 2
#define SEQ 2048
#define ROWS (BATCH * SEQ)   // 4096

// ---------------- scratch (allocation-free: __device__ globals) ----------------
__device__ float g_qkv[(size_t)ROWS * 3 * D_MODEL];
__device__ float g_x1 [(size_t)ROWS * D_MODEL];
__device__ float g_h  [(size_t)ROWS * 2 * HIDDEN];
__device__ __nv_bfloat16 g_xnhi [(size_t)ROWS * D_MODEL];
__device__ __nv_bfloat16 g_xnlo [(size_t)ROWS * D_MODEL];
__device__ __nv_bfloat16 g_atthi[(size_t)ROWS * D_MODEL];
__device__ __nv_bfloat16 g_attlo[(size_t)ROWS * D_MODEL];
__device__ __nv_bfloat16 g_ffnhi[(size_t)ROWS * HIDDEN];
__device__ __nv_bfloat16 g_ffnlo[(size_t)ROWS * HIDDEN];
// transposed+split weights [N,K], concatenated:
//   [0)        qkvT  3072x1024
//   [3145728)  oT    1024x1024
//   [4194304)  w1T   8192x1024
//   [12582912) w2T   1024x4096
__device__ __nv_bfloat16 g_wthi[16777216];
__device__ __nv_bfloat16 g_wtlo[16777216];

// ---------------- helpers ----------------
__device__ __forceinline__ uint32_t smem_u32(const void* p) {
    uint32_t a;
    asm("{ .reg .u64 t; cvta.to.shared.u64 t, %1; cvt.u32.u64 %0, t; }"
        : "=r"(a) : "l"(p));
    return a;
}
__device__ __forceinline__ void cp16(void* dst_smem, const void* src) {
    uint32_t d = smem_u32(dst_smem);
    asm volatile("cp.async.cg.shared.global [%0], [%1], 16;" :: "r"(d), "l"(src));
}
__device__ __forceinline__ void cp_commit() {
    asm volatile("cp.async.commit_group;" ::: "memory");
}
template<int N> __device__ __forceinline__ void cp_wait() {
    asm volatile("cp.async.wait_group %0;" :: "n"(N) : "memory");
}

__device__ __forceinline__ void bf16_split(float v, __nv_bfloat16& hi, __nv_bfloat16& lo) {
    hi = __float2bfloat16_rn(v);
    lo = __float2bfloat16_rn(v - __bfloat162float(hi));
}

// ---------------- weight transpose + bf16 split: W[K,N] -> Wt hi/lo [N,K] ----------------
__global__ __launch_bounds__(256) void wsplit_kernel(
    const float* __restrict__ W, int K, int N,
    __nv_bfloat16* __restrict__ Thi, __nv_bfloat16* __restrict__ Tlo)
{
    __shared__ float t[32][33];
    int tx = threadIdx.x & 31, ty = threadIdx.x >> 5;  // 32x8
    int n0 = blockIdx.x * 32, k0 = blockIdx.y * 32;
    #pragma unroll
    for (int j = 0; j < 4; j++)
        t[ty + j * 8][tx] = W[(size_t)(k0 + ty + j * 8) * N + n0 + tx];
    __syncthreads();
    #pragma unroll
    for (int j = 0; j < 4; j++) {
        int n = n0 + ty + j * 8, k = k0 + tx;
        float v = t[tx][ty + j * 8];
        __nv_bfloat16 hi, lo; bf16_split(v, hi, lo);
        Thi[(size_t)n * K + k] = hi;
        Tlo[(size_t)n * K + k] = lo;
    }
}

// ---------------- RMSNorm -> bf16 hi/lo ----------------
__global__ __launch_bounds__(256) void rmsnorm_kernel(
    const float* __restrict__ x, const float* __restrict__ scale,
    __nv_bfloat16* __restrict__ yhi, __nv_bfloat16* __restrict__ ylo)
{
    int row = blockIdx.x;
    const float* xr = x + (size_t)row * D_MODEL;
    int t = threadIdx.x;
    float v0 = xr[t], v1 = xr[t + 256], v2 = xr[t + 512], v3 = xr[t + 768];
    float ss = v0*v0 + v1*v1 + v2*v2 + v3*v3;
    #pragma unroll
    for (int o = 16; o; o >>= 1) ss += __shfl_xor_sync(0xffffffffu, ss, o);
    __shared__ float red[8];
    if ((t & 31) == 0) red[t >> 5] = ss;
    __syncthreads();
    float tot = 0.f;
    #pragma unroll
    for (int w = 0; w < 8; w++) tot += red[w];
    float r = rsqrtf(tot * (1.0f / D_MODEL) + 1e-8f);
    size_t base = (size_t)row * D_MODEL;
    #pragma unroll
    for (int q = 0; q < 4; q++) {
        int c = t + q * 256;
        float v = (q == 0 ? v0 : q == 1 ? v1 : q == 2 ? v2 : v3);
        float y = scale[c] * v * r;
        __nv_bfloat16 hi, lo; bf16_split(y, hi, lo);
        yhi[base + c] = hi; ylo[base + c] = lo;
    }
}

// ---------------- wmma bf16x3 GEMM: C[M,N] = A[M,K] @ Bt[N,K]^T + bias (+res) ------
// CTA 128x128, 8 warps (4x2), warp tile 32x64 = 2x4 wmma 16x16x16 frags.
// BK=32, cp.async double-buffered. A,B tiles in smem padded to 40 bf16/row.
#define BKP 40
#define TILE_E (128 * BKP)                 // bf16 elems per tile
#define STG_E  (4 * TILE_E)                // elems per stage (Ahi,Alo,Bhi,Blo)
#define GSMEM  (2 * STG_E * 2)             // bytes (2 stages, bf16)

__global__ __launch_bounds__(256) void wmma_gemm(
    const __nv_bfloat16* __restrict__ Ahi, const __nv_bfloat16* __restrict__ Alo,
    const __nv_bfloat16* __restrict__ Bhi, const __nv_bfloat16* __restrict__ Blo,
    const float* __restrict__ bias, const float* __restrict__ res,
    float* __restrict__ C, int M, int N, int K)
{
    extern __shared__ __nv_bfloat16 sm[];
    int tid = threadIdx.x, wid = tid >> 5, lane = tid & 31;
    int bm = blockIdx.y, bn = blockIdx.x;
    int wm = wid >> 1, wn = wid & 1;

    wmma::fragment<wmma::accumulator, 16, 16, 16, float> acc[2][4];
    #pragma unroll
    for (int i = 0; i < 2; i++)
        #pragma unroll
        for (int j = 0; j < 4; j++) wmma::fill_fragment(acc[i][j], 0.f);

    const __nv_bfloat16* gb0 = Ahi + (size_t)bm * 128 * K;
    const __nv_bfloat16* gb1 = Alo + (size_t)bm * 128 * K;
    const __nv_bfloat16* gb2 = Bhi + (size_t)bn * 128 * K;
    const __nv_bfloat16* gb3 = Blo + (size_t)bn * 128 * K;

    const int S = K >> 5;   // stages of 32
    int ld_row = tid >> 1;              // 0..127
    int ld_seg = (tid & 1) << 1;        // 0 or 2  (two 16B segs per thread per tile)

    // ---- prologue: stage 0 ----
    {
        __nv_bfloat16* st = sm;
        size_t go = (size_t)ld_row * K + ld_seg * 8;
        uint32_t so = ld_row * BKP + ld_seg * 8;
        cp16(st + so,              gb0 + go);
        cp16(st + so + 8,          gb0 + go + 8);
        cp16(st + TILE_E + so,     gb1 + go);
        cp16(st + TILE_E + so + 8, gb1 + go + 8);
        cp16(st + 2*TILE_E + so,     gb2 + go);
        cp16(st + 2*TILE_E + so + 8, gb2 + go + 8);
        cp16(st + 3*TILE_E + so,     gb3 + go);
        cp16(st + 3*TILE_E + so + 8, gb3 + go + 8);
        cp_commit();
    }

    for (int s = 0; s < S; s++) {
        if (s + 1 < S) {
            __nv_bfloat16* st = sm + ((s + 1) & 1) * STG_E;
            size_t go = (size_t)ld_row * K + ((s + 1) << 5) + ld_seg * 8;
            uint32_t so = ld_row * BKP + ld_seg * 8;
            cp16(st + so,              gb0 + go);
            cp16(st + so + 8,          gb0 + go + 8);
            cp16(st + TILE_E + so,     gb1 + go);
            cp16(st + TILE_E + so + 8, gb1 + go + 8);
            cp16(st + 2*TILE_E + so,     gb2 + go);
            cp16(st + 2*TILE_E + so + 8, gb2 + go + 8);
            cp16(st + 3*TILE_E + so,     gb3 + go);
            cp16(st + 3*TILE_E + so + 8, gb3 + go + 8);
            cp_commit();
            cp_wait<1>();
        } else {
            cp_wait<0>();
        }
        __syncthreads();

        __nv_bfloat16* st = sm + (s & 1) * STG_E;
        const __nv_bfloat16* As_hi = st;
        const __nv_bfloat16* As_lo = st + TILE_E;
        const __nv_bfloat16* Bs_hi = st + 2 * TILE_E;
        const __nv_bfloat16* Bs_lo = st + 3 * TILE_E;

        #pragma unroll
        for (int kk = 0; kk < 32; kk += 16) {
            wmma::fragment<wmma::matrix_a, 16, 16, 16, __nv_bfloat16, wmma::row_major> ah[2], al[2];
            wmma::fragment<wmma::matrix_b, 16, 16, 16, __nv_bfloat16, wmma::col_major> bh[4], bl[4];
            #pragma unroll
            for (int i = 0; i < 2; i++) {
                int r0 = (wm * 32 + i * 16) * BKP + kk;
                wmma::load_matrix_sync(ah[i], As_hi + r0, BKP);
                wmma::load_matrix_sync(al[i], As_lo + r0, BKP);
            }
            #pragma unroll
            for (int j = 0; j < 4; j++) {
                int r0 = (wn * 64 + j * 16) * BKP + kk;
                wmma::load_matrix_sync(bh[j], Bs_hi + r0, BKP);
                wmma::load_matrix_sync(bl[j], Bs_lo + r0, BKP);
            }
            #pragma unroll
            for (int i = 0; i < 2; i++)
                #pragma unroll
                for (int j = 0; j < 4; j++) {
                    wmma::mma_sync(acc[i][j], ah[i], bh[j], acc[i][j]);
                    wmma::mma_sync(acc[i][j], ah[i], bl[j], acc[i][j]);
                    wmma::mma_sync(acc[i][j], al[i], bh[j], acc[i][j]);
                }
        }
        __syncthreads();
    }

    // epilogue: stage accumulators through smem, fuse bias (+res)
    float* stg  = (float*)sm;
    float* wstg = stg + wid * 32 * 68;
    #pragma unroll
    for (int i = 0; i < 2; i++)
        #pragma unroll
        for (int j = 0; j < 4; j++)
            wmma::store_matrix_sync(wstg + i * 16 * 68 + j * 16, acc[i][j], 68,
                                    wmma::mem_row_major);
    __syncwarp();

    int row  = bm * 128 + wm * 32 + lane;
    int col0 = bn * 128 + wn * 64;
    float* Cr = C + (size_t)row * N + col0;
    const float* br = bias + col0;
    const float* rr = res ? res + (size_t)row * N + col0 : nullptr;
    const float* srow = wstg + lane * 68;
    #pragma unroll
    for (int c = 0; c < 16; c++) {
        float4 o = *(const float4*)(srow + c * 4);
        float4 bv = *(const float4*)(br + c * 4);
        o.x += bv.x; o.y += bv.y; o.z += bv.z; o.w += bv.w;
        if (rr) {
            float4 rv = *(const float4*)(rr + c * 4);
            o.x += rv.x; o.y += rv.y; o.z += rv.z; o.w += rv.w;
        }
        *(float4*)(Cr + c * 4) = o;
    }
}

// ---------------- Flash attention (causal + analytic ALiBi) -> bf16 hi/lo out ----
#define FST 65
#define NEG_INF -1e30f
#define INV_SQRT_DH 0.125f

__global__ __launch_bounds__(256) void flash_attn_kernel(
    const float* __restrict__ qkv,
    __nv_bfloat16* __restrict__ ohi, __nv_bfloat16* __restrict__ olo)
{
    extern __shared__ float smf[];
    float* Qs = smf;
    float* Ks = smf + 64 * FST;
    float* Vs = smf + 2 * 64 * FST;
    float* Ps = smf + 3 * 64 * FST;

    int qt = blockIdx.x;
    int bh = blockIdx.y;
    int b  = bh >> 4, h = bh & 15;
    float slope = exp2f(-0.5f * (float)(h + 1));

    int tid = threadIdx.x;
    int tm = tid >> 4, tn = tid & 15;
    int r0 = tm << 2, c0 = tn << 2;

    {
        int r  = tid >> 2;
        int cl = (tid & 3) << 4;
        const float* src = qkv + (size_t)(b * SEQ + qt * 64 + r) * 3072 + h * 64 + cl;
        float* dst = Qs + r * FST + cl;
        #pragma unroll
        for (int t = 0; t < 4; t++) {
            float4 v = *reinterpret_cast<const float4*>(src + t * 4);
            dst[t*4+0] = v.x; dst[t*4+1] = v.y; dst[t*4+2] = v.z; dst[t*4+3] = v.w;
        }
    }

    float m_i[4], l_i[4], o[4][4];
    #pragma unroll
    for (int i = 0; i < 4; i++) {
        m_i[i] = NEG_INF; l_i[i] = 0.f;
        #pragma unroll
        for (int j = 0; j < 4; j++) o[i][j] = 0.f;
    }

    for (int kt = 0; kt <= qt; kt++) {
        {
            int r  = tid >> 2;
            int cl = (tid & 3) << 4;
            const float* srck = qkv + (size_t)(b * SEQ + kt * 64 + r) * 3072 + 1024 + h * 64 + cl;
            const float* srcv = srck + 1024;
            float* dk = Ks + r * FST + cl;
            float* dv = Vs + r * FST + cl;
            #pragma unroll
            for (int t = 0; t < 4; t++) {
                float4 vk = *reinterpret_cast<const float4*>(srck + t * 4);
                float4 vv = *reinterpret_cast<const float4*>(srcv + t * 4);
                dk[t*4+0] = vk.x; dk[t*4+1] = vk.y; dk[t*4+2] = vk.z; dk[t*4+3] = vk.w;
                dv[t*4+0] = vv.x; dv[t*4+1] = vv.y; dv[t*4+2] = vv.z; dv[t*4+3] = vv.w;
            }
        }
        __syncthreads();

        float s[4][4];
        #pragma unroll
        for (int i = 0; i < 4; i++)
            #pragma unroll
            for (int j = 0; j < 4; j++) s[i][j] = 0.f;
        #pragma unroll 8
        for (int d = 0; d < 64; d++) {
            float qv[4], kv[4];
            #pragma unroll
            for (int i = 0; i < 4; i++) qv[i] = Qs[(r0 + i) * FST + d];
            #pragma unroll
            for (int j = 0; j < 4; j++) kv[j] = Ks[(c0 + j) * FST + d];
            #pragma unroll
            for (int i = 0; i < 4; i++)
                #pragma unroll
                for (int j = 0; j < 4; j++)
                    s[i][j] = fmaf(qv[i], kv[j], s[i][j]);
        }

        int ibase = qt * 64 + r0, jbase = kt * 64 + c0;
        #pragma unroll
        for (int i = 0; i < 4; i++) {
            int ii = ibase + i;
            float rmax = NEG_INF;
            #pragma unroll
            for (int j = 0; j < 4; j++) {
                int jj = jbase + j;
                float val = s[i][j] * INV_SQRT_DH - slope * (float)(ii - jj);
                if (jj > ii) val = NEG_INF;
                s[i][j] = val;
                rmax = fmaxf(rmax, val);
            }
            #pragma unroll
            for (int off = 8; off; off >>= 1)
                rmax = fmaxf(rmax, __shfl_xor_sync(0xffffffffu, rmax, off, 16));
            float mnew = fmaxf(m_i[i], rmax);
            float corr = __expf(m_i[i] - mnew);
            m_i[i] = mnew;
            float psum = 0.f;
            #pragma unroll
            for (int j = 0; j < 4; j++) {
                float p = __expf(s[i][j] - mnew);
                s[i][j] = p;
                psum += p;
            }
            #pragma unroll
            for (int off = 8; off; off >>= 1)
                psum += __shfl_xor_sync(0xffffffffu, psum, off, 16);
            l_i[i] = l_i[i] * corr + psum;
            #pragma unroll
            for (int j = 0; j < 4; j++) {
                o[i][j] *= corr;
                Ps[(r0 + i) * FST + c0 + j] = s[i][j];
            }
        }
        __syncthreads();

        #pragma unroll 8
        for (int c = 0; c < 64; c++) {
            float pv[4], vv[4];
            #pragma unroll
            for (int i = 0; i < 4; i++) pv[i] = Ps[(r0 + i) * FST + c];
            #pragma unroll
            for (int j = 0; j < 4; j++) vv[j] = Vs[c * FST + c0 + j];
            #pragma unroll
            for (int i = 0; i < 4; i++)
                #pragma unroll
                for (int j = 0; j < 4; j++)
                    o[i][j] = fmaf(pv[i], vv[j], o[i][j]);
        }
        __syncthreads();
    }

    #pragma unroll
    for (int i = 0; i < 4; i++) {
        float inv = 1.0f / l_i[i];
        size_t off = (size_t)(b * SEQ + qt * 64 + r0 + i) * D_MODEL + h * 64 + c0;
        #pragma unroll
        for (int j = 0; j < 4; j++) {
            __nv_bfloat16 hi, lo; bf16_split(o[i][j] * inv, hi, lo);
            ohi[off + j] = hi; olo[off + j] = lo;
        }
    }
}

// ---------------- SwiGLU -> bf16 hi/lo ----------------
__global__ __launch_bounds__(256) void swiglu_kernel(
    const float* __restrict__ h,
    __nv_bfloat16* __restrict__ ghi, __nv_bfloat16* __restrict__ glo)
{
    int idx = blockIdx.x * 256 + threadIdx.x;
    int r = idx >> 12;
    int j = idx & 4095;
    const float* hr = h + (size_t)r * (2 * HIDDEN);
    float xp = hr[j];
    float gt = hr[j + HIDDEN];
    float sg = 1.0f / (1.0f + __expf(-gt));
    float v = gt * sg * xp;
    __nv_bfloat16 hi, lo; bf16_split(v, hi, lo);
    ghi[idx] = hi; glo[idx] = lo;
}

// ---------------- launch ----------------
extern "C" void kernel_launch(void* const* d_in, const int* in_sizes, int n_in,
                              void* d_out, int out_size)
{
    const float* x      = (const float*)d_in[0];
    const float* w_qkv  = (const float*)d_in[3];
    const float* b_qkv  = (const float*)d_in[4];
    const float* w_o    = (const float*)d_in[5];
    const float* b_o    = (const float*)d_in[6];
    const float* scale1 = (const float*)d_in[7];
    const float* scale2 = (const float*)d_in[8];
    const float* w1     = (const float*)d_in[9];
    const float* b1     = (const float*)d_in[10];
    const float* w2     = (const float*)d_in[11];
    const float* b2     = (const float*)d_in[12];
    float* out = (float*)d_out;

    float *qkvp, *x1, *hbuf;
    __nv_bfloat16 *xnhi, *xnlo, *atthi, *attlo, *ffnhi, *ffnlo, *wthi, *wtlo;
    cudaGetSymbolAddress((void**)&qkvp,  g_qkv);
    cudaGetSymbolAddress((void**)&x1,    g_x1);
    cudaGetSymbolAddress((void**)&hbuf,  g_h);
    cudaGetSymbolAddress((void**)&xnhi,  g_xnhi);
    cudaGetSymbolAddress((void**)&xnlo,  g_xnlo);
    cudaGetSymbolAddress((void**)&atthi, g_atthi);
    cudaGetSymbolAddress((void**)&attlo, g_attlo);
    cudaGetSymbolAddress((void**)&ffnhi, g_ffnhi);
    cudaGetSymbolAddress((void**)&ffnlo, g_ffnlo);
    cudaGetSymbolAddress((void**)&wthi,  g_wthi);
    cudaGetSymbolAddress((void**)&wtlo,  g_wtlo);

    cudaFuncSetAttribute(wmma_gemm, cudaFuncAttributeMaxDynamicSharedMemorySize, GSMEM);
    int fa_smem = 4 * 64 * FST * (int)sizeof(float);
    cudaFuncSetAttribute(flash_attn_kernel,
                         cudaFuncAttributeMaxDynamicSharedMemorySize, fa_smem);

    const size_t OFF_QKV = 0, OFF_O = 3145728, OFF_W1 = 4194304, OFF_W2 = 12582912;

    // 0) transpose + split weights
    wsplit_kernel<<<dim3(3072/32, 1024/32), 256>>>(w_qkv, 1024, 3072, wthi+OFF_QKV, wtlo+OFF_QKV);
    wsplit_kernel<<<dim3(1024/32, 1024/32), 256>>>(w_o,   1024, 1024, wthi+OFF_O,   wtlo+OFF_O);
    wsplit_kernel<<<dim3(8192/32, 1024/32), 256>>>(w1,    1024, 8192, wthi+OFF_W1,  wtlo+OFF_W1);
    wsplit_kernel<<<dim3(1024/32, 4096/32), 256>>>(w2,    4096, 1024, wthi+OFF_W2,  wtlo+OFF_W2);

    // 1) xn = rmsnorm(x, scale1) -> hi/lo
    rmsnorm_kernel<<<ROWS, 256>>>(x, scale1, xnhi, xnlo);
    // 2) qkv = xn @ w_qkv + b_qkv
    wmma_gemm<<<dim3(3072/128, ROWS/128), 256, GSMEM>>>(
        xnhi, xnlo, wthi+OFF_QKV, wtlo+OFF_QKV, b_qkv, nullptr, qkvp, ROWS, 3072, 1024);
    // 3) attention
    flash_attn_kernel<<<dim3(SEQ/64, BATCH*NHEAD), 256, fa_smem>>>(qkvp, atthi, attlo);
    // 4) x1 = x + att @ w_o + b_o
    wmma_gemm<<<dim3(1024/128, ROWS/128), 256, GSMEM>>>(
        atthi, attlo, wthi+OFF_O, wtlo+OFF_O, b_o, x, x1, ROWS, 1024, 1024);
    // 5) xn = rmsnorm(x1, scale2) -> hi/lo
    rmsnorm_kernel<<<ROWS, 256>>>(x1, scale2, xnhi, xnlo);
    // 6) h = xn @ w1 + b1
    wmma_gemm<<<dim3(8192/128, ROWS/128), 256, GSMEM>>>(
        xnhi, xnlo, wthi+OFF_W1, wtlo+OFF_W1, b1, nullptr, hbuf, ROWS, 8192, 1024);
    // 7) ffn = silu(gate) * x_proj -> hi/lo
    swiglu_kernel<<<ROWS * HIDDEN / 256, 256>>>(hbuf, ffnhi, ffnlo);
    // 8) out = x1 + ffn @ w2 + b2
    wmma_gemm<<<dim3(1024/128, ROWS/128), 256, GSMEM>>>(
        ffnhi, ffnlo, wthi+OFF_W2, wtlo+OFF_W2, b2, x1, out, ROWS, 1024, 4096);
}

// round 8
// speedup vs baseline: 2.1466x; 1.3971x over previous
#include <cuda_runtime.h>
#include <cuda_fp16.h>
#include <mma.h>
#include <math.h>
#include <stdint.h>

using namespace nvcuda;

#define D_MODEL 1024
#define NHEAD 16
#define HEAD_DIM 64
#define HIDDEN 4096
#define BATCH 2
#define SEQ 2048
#define ROWS (BATCH * SEQ)   // 4096

// ---------------- scratch (allocation-free: __device__ globals) ----------------
__device__ float g_qkv[(size_t)ROWS * 3 * D_MODEL];
__device__ float g_x1 [(size_t)ROWS * D_MODEL];
__device__ float g_h  [(size_t)ROWS * 2 * HIDDEN];
__device__ __half g_xn  [(size_t)ROWS * D_MODEL];
__device__ __half g_att [(size_t)ROWS * D_MODEL];
__device__ __half g_ffn [(size_t)ROWS * HIDDEN];
// transposed+split weights [N,K], concatenated:
//   [0)        qkvT  3072x1024
//   [3145728)  oT    1024x1024
//   [4194304)  w1T   8192x1024
//   [12582912) w2T   1024x4096
__device__ __half g_wthi[16777216];
__device__ __half g_wtlo[16777216];

// ---------------- helpers ----------------
__device__ __forceinline__ uint32_t smem_u32(const void* p) {
    uint32_t a;
    asm("{ .reg .u64 t; cvta.to.shared.u64 t, %1; cvt.u32.u64 %0, t; }"
        : "=r"(a) : "l"(p));
    return a;
}
__device__ __forceinline__ void cp16(void* dst_smem, const void* src) {
    uint32_t d = smem_u32(dst_smem);
    asm volatile("cp.async.cg.shared.global [%0], [%1], 16;" :: "r"(d), "l"(src));
}
__device__ __forceinline__ void cp_commit() {
    asm volatile("cp.async.commit_group;" ::: "memory");
}
template<int N> __device__ __forceinline__ void cp_wait() {
    asm volatile("cp.async.wait_group %0;" :: "n"(N) : "memory");
}

__device__ __forceinline__ void fp16_split(float v, __half& hi, __half& lo) {
    hi = __float2half_rn(v);
    lo = __float2half_rn(v - __half2float(hi));
}

// ---------------- weight transpose + fp16 split: W[K,N] -> Wt hi/lo [N,K] ----------------
__global__ __launch_bounds__(256) void wsplit_kernel(
    const float* __restrict__ W, int K, int N,
    __half* __restrict__ Thi, __half* __restrict__ Tlo)
{
    __shared__ float t[32][33];
    int tx = threadIdx.x & 31, ty = threadIdx.x >> 5;  // 32x8
    int n0 = blockIdx.x * 32, k0 = blockIdx.y * 32;
    #pragma unroll
    for (int j = 0; j < 4; j++)
        t[ty + j * 8][tx] = W[(size_t)(k0 + ty + j * 8) * N + n0 + tx];
    __syncthreads();
    #pragma unroll
    for (int j = 0; j < 4; j++) {
        int n = n0 + ty + j * 8, k = k0 + tx;
        float v = t[tx][ty + j * 8];
        __half hi, lo; fp16_split(v, hi, lo);
        Thi[(size_t)n * K + k] = hi;
        Tlo[(size_t)n * K + k] = lo;
    }
}

// ---------------- RMSNorm -> fp16 ----------------
__global__ __launch_bounds__(256) void rmsnorm_kernel(
    const float* __restrict__ x, const float* __restrict__ scale,
    __half* __restrict__ y)
{
    int row = blockIdx.x;
    const float* xr = x + (size_t)row * D_MODEL;
    int t = threadIdx.x;
    float v0 = xr[t], v1 = xr[t + 256], v2 = xr[t + 512], v3 = xr[t + 768];
    float ss = v0*v0 + v1*v1 + v2*v2 + v3*v3;
    #pragma unroll
    for (int o = 16; o; o >>= 1) ss += __shfl_xor_sync(0xffffffffu, ss, o);
    __shared__ float red[8];
    if ((t & 31) == 0) red[t >> 5] = ss;
    __syncthreads();
    float tot = 0.f;
    #pragma unroll
    for (int w = 0; w < 8; w++) tot += red[w];
    float r = rsqrtf(tot * (1.0f / D_MODEL) + 1e-8f);
    size_t base = (size_t)row * D_MODEL;
    y[base + t]       = __float2half_rn(scale[t]       * v0 * r);
    y[base + t + 256] = __float2half_rn(scale[t + 256] * v1 * r);
    y[base + t + 512] = __float2half_rn(scale[t + 512] * v2 * r);
    y[base + t + 768] = __float2half_rn(scale[t + 768] * v3 * r);
}

// ---------------- wmma fp16x2 GEMM: C[M,N] = A[M,K] @ Bt[N,K]^T + bias (+res) ------
// CTA 128x128, 8 warps (4x2), warp tile 32x64 = 2x4 wmma 16x16x16 frags.
// BK=32, cp.async double-buffered. Tiles: A (fp16), Bhi, Blo; padded to 40 half/row.
#define BKP 40
#define TILE_E (128 * BKP)                 // half elems per tile (5120)
#define STG_E  (3 * TILE_E)                // elems per stage (A,Bhi,Blo)
#define GSMEM  69632                       // max(2*STG_E*2 = 61440, epilogue 8*32*68*4)

__global__ __launch_bounds__(256) void wmma_gemm(
    const __half* __restrict__ A,
    const __half* __restrict__ Bhi, const __half* __restrict__ Blo,
    const float* __restrict__ bias, const float* __restrict__ res,
    float* __restrict__ C, int M, int N, int K)
{
    extern __shared__ __half sm[];
    int tid = threadIdx.x, wid = tid >> 5, lane = tid & 31;
    int bm = blockIdx.y, bn = blockIdx.x;
    int wm = wid >> 1, wn = wid & 1;

    wmma::fragment<wmma::accumulator, 16, 16, 16, float> acc[2][4];
    #pragma unroll
    for (int i = 0; i < 2; i++)
        #pragma unroll
        for (int j = 0; j < 4; j++) wmma::fill_fragment(acc[i][j], 0.f);

    const __half* gb0 = A   + (size_t)bm * 128 * K;
    const __half* gb1 = Bhi + (size_t)bn * 128 * K;
    const __half* gb2 = Blo + (size_t)bn * 128 * K;

    const int S = K >> 5;   // stages of 32
    int ld_row = tid >> 1;              // 0..127
    int ld_seg = (tid & 1) << 1;        // 0 or 2 (two 16B segs of the 4 per row)

    // ---- prologue: stage 0 ----
    {
        __half* st = sm;
        size_t go = (size_t)ld_row * K + ld_seg * 8;
        uint32_t so = ld_row * BKP + ld_seg * 8;
        cp16(st + so,                gb0 + go);
        cp16(st + so + 8,            gb0 + go + 8);
        cp16(st + TILE_E + so,       gb1 + go);
        cp16(st + TILE_E + so + 8,   gb1 + go + 8);
        cp16(st + 2*TILE_E + so,     gb2 + go);
        cp16(st + 2*TILE_E + so + 8, gb2 + go + 8);
        cp_commit();
    }

    for (int s = 0; s < S; s++) {
        if (s + 1 < S) {
            __half* st = sm + ((s + 1) & 1) * STG_E;
            size_t go = (size_t)ld_row * K + ((s + 1) << 5) + ld_seg * 8;
            uint32_t so = ld_row * BKP + ld_seg * 8;
            cp16(st + so,                gb0 + go);
            cp16(st + so + 8,            gb0 + go + 8);
            cp16(st + TILE_E + so,       gb1 + go);
            cp16(st + TILE_E + so + 8,   gb1 + go + 8);
            cp16(st + 2*TILE_E + so,     gb2 + go);
            cp16(st + 2*TILE_E + so + 8, gb2 + go + 8);
            cp_commit();
            cp_wait<1>();
        } else {
            cp_wait<0>();
        }
        __syncthreads();

        __half* st = sm + (s & 1) * STG_E;
        const __half* As    = st;
        const __half* Bs_hi = st + TILE_E;
        const __half* Bs_lo = st + 2 * TILE_E;

        #pragma unroll
        for (int kk = 0; kk < 32; kk += 16) {
            wmma::fragment<wmma::matrix_a, 16, 16, 16, __half, wmma::row_major> a[2];
            wmma::fragment<wmma::matrix_b, 16, 16, 16, __half, wmma::col_major> bh[4], bl[4];
            #pragma unroll
            for (int i = 0; i < 2; i++)
                wmma::load_matrix_sync(a[i], As + (wm * 32 + i * 16) * BKP + kk, BKP);
            #pragma unroll
            for (int j = 0; j < 4; j++) {
                int r0 = (wn * 64 + j * 16) * BKP + kk;
                wmma::load_matrix_sync(bh[j], Bs_hi + r0, BKP);
                wmma::load_matrix_sync(bl[j], Bs_lo + r0, BKP);
            }
            #pragma unroll
            for (int i = 0; i < 2; i++)
                #pragma unroll
                for (int j = 0; j < 4; j++) {
                    wmma::mma_sync(acc[i][j], a[i], bh[j], acc[i][j]);
                    wmma::mma_sync(acc[i][j], a[i], bl[j], acc[i][j]);
                }
        }
        __syncthreads();
    }

    // epilogue: stage accumulators through smem, fuse bias (+res)
    float* stg  = (float*)sm;
    float* wstg = stg + wid * 32 * 68;
    #pragma unroll
    for (int i = 0; i < 2; i++)
        #pragma unroll
        for (int j = 0; j < 4; j++)
            wmma::store_matrix_sync(wstg + i * 16 * 68 + j * 16, acc[i][j], 68,
                                    wmma::mem_row_major);
    __syncwarp();

    int row  = bm * 128 + wm * 32 + lane;
    int col0 = bn * 128 + wn * 64;
    float* Cr = C + (size_t)row * N + col0;
    const float* br = bias + col0;
    const float* rr = res ? res + (size_t)row * N + col0 : nullptr;
    const float* srow = wstg + lane * 68;
    #pragma unroll
    for (int c = 0; c < 16; c++) {
        float4 o = *(const float4*)(srow + c * 4);
        float4 bv = *(const float4*)(br + c * 4);
        o.x += bv.x; o.y += bv.y; o.z += bv.z; o.w += bv.w;
        if (rr) {
            float4 rv = *(const float4*)(rr + c * 4);
            o.x += rv.x; o.y += rv.y; o.z += rv.z; o.w += rv.w;
        }
        *(float4*)(Cr + c * 4) = o;
    }
}

// ---------------- Flash attention (causal + analytic ALiBi) -> fp16 out ----
#define FST 65
#define NEG_INF -1e30f
#define INV_SQRT_DH 0.125f

__global__ __launch_bounds__(256) void flash_attn_kernel(
    const float* __restrict__ qkv, __half* __restrict__ outp)
{
    extern __shared__ float smf[];
    float* Qs = smf;
    float* Ks = smf + 64 * FST;
    float* Vs = smf + 2 * 64 * FST;
    float* Ps = smf + 3 * 64 * FST;

    int qt = blockIdx.x;
    int bh = blockIdx.y;
    int b  = bh >> 4, h = bh & 15;
    float slope = exp2f(-0.5f * (float)(h + 1));

    int tid = threadIdx.x;
    int tm = tid >> 4, tn = tid & 15;
    int r0 = tm << 2, c0 = tn << 2;

    {
        int r  = tid >> 2;
        int cl = (tid & 3) << 4;
        const float* src = qkv + (size_t)(b * SEQ + qt * 64 + r) * 3072 + h * 64 + cl;
        float* dst = Qs + r * FST + cl;
        #pragma unroll
        for (int t = 0; t < 4; t++) {
            float4 v = *reinterpret_cast<const float4*>(src + t * 4);
            dst[t*4+0] = v.x; dst[t*4+1] = v.y; dst[t*4+2] = v.z; dst[t*4+3] = v.w;
        }
    }

    float m_i[4], l_i[4], o[4][4];
    #pragma unroll
    for (int i = 0; i < 4; i++) {
        m_i[i] = NEG_INF; l_i[i] = 0.f;
        #pragma unroll
        for (int j = 0; j < 4; j++) o[i][j] = 0.f;
    }

    for (int kt = 0; kt <= qt; kt++) {
        {
            int r  = tid >> 2;
            int cl = (tid & 3) << 4;
            const float* srck = qkv + (size_t)(b * SEQ + kt * 64 + r) * 3072 + 1024 + h * 64 + cl;
            const float* srcv = srck + 1024;
            float* dk = Ks + r * FST + cl;
            float* dv = Vs + r * FST + cl;
            #pragma unroll
            for (int t = 0; t < 4; t++) {
                float4 vk = *reinterpret_cast<const float4*>(srck + t * 4);
                float4 vv = *reinterpret_cast<const float4*>(srcv + t * 4);
                dk[t*4+0] = vk.x; dk[t*4+1] = vk.y; dk[t*4+2] = vk.z; dk[t*4+3] = vk.w;
                dv[t*4+0] = vv.x; dv[t*4+1] = vv.y; dv[t*4+2] = vv.z; dv[t*4+3] = vv.w;
            }
        }
        __syncthreads();

        float s[4][4];
        #pragma unroll
        for (int i = 0; i < 4; i++)
            #pragma unroll
            for (int j = 0; j < 4; j++) s[i][j] = 0.f;
        #pragma unroll 8
        for (int d = 0; d < 64; d++) {
            float qv[4], kv[4];
            #pragma unroll
            for (int i = 0; i < 4; i++) qv[i] = Qs[(r0 + i) * FST + d];
            #pragma unroll
            for (int j = 0; j < 4; j++) kv[j] = Ks[(c0 + j) * FST + d];
            #pragma unroll
            for (int i = 0; i < 4; i++)
                #pragma unroll
                for (int j = 0; j < 4; j++)
                    s[i][j] = fmaf(qv[i], kv[j], s[i][j]);
        }

        int ibase = qt * 64 + r0, jbase = kt * 64 + c0;
        #pragma unroll
        for (int i = 0; i < 4; i++) {
            int ii = ibase + i;
            float rmax = NEG_INF;
            #pragma unroll
            for (int j = 0; j < 4; j++) {
                int jj = jbase + j;
                float val = s[i][j] * INV_SQRT_DH - slope * (float)(ii - jj);
                if (jj > ii) val = NEG_INF;
                s[i][j] = val;
                rmax = fmaxf(rmax, val);
            }
            #pragma unroll
            for (int off = 8; off; off >>= 1)
                rmax = fmaxf(rmax, __shfl_xor_sync(0xffffffffu, rmax, off, 16));
            float mnew = fmaxf(m_i[i], rmax);
            float corr = __expf(m_i[i] - mnew);
            m_i[i] = mnew;
            float psum = 0.f;
            #pragma unroll
            for (int j = 0; j < 4; j++) {
                float p = __expf(s[i][j] - mnew);
                s[i][j] = p;
                psum += p;
            }
            #pragma unroll
            for (int off = 8; off; off >>= 1)
                psum += __shfl_xor_sync(0xffffffffu, psum, off, 16);
            l_i[i] = l_i[i] * corr + psum;
            #pragma unroll
            for (int j = 0; j < 4; j++) {
                o[i][j] *= corr;
                Ps[(r0 + i) * FST + c0 + j] = s[i][j];
            }
        }
        __syncthreads();

        #pragma unroll 8
        for (int c = 0; c < 64; c++) {
            float pv[4], vv[4];
            #pragma unroll
            for (int i = 0; i < 4; i++) pv[i] = Ps[(r0 + i) * FST + c];
            #pragma unroll
            for (int j = 0; j < 4; j++) vv[j] = Vs[c * FST + c0 + j];
            #pragma unroll
            for (int i = 0; i < 4; i++)
                #pragma unroll
                for (int j = 0; j < 4; j++)
                    o[i][j] = fmaf(pv[i], vv[j], o[i][j]);
        }
        __syncthreads();
    }

    #pragma unroll
    for (int i = 0; i < 4; i++) {
        float inv = 1.0f / l_i[i];
        size_t off = (size_t)(b * SEQ + qt * 64 + r0 + i) * D_MODEL + h * 64 + c0;
        #pragma unroll
        for (int j = 0; j < 4; j++)
            outp[off + j] = __float2half_rn(o[i][j] * inv);
    }
}

// ---------------- SwiGLU -> fp16 ----------------
__global__ __launch_bounds__(256) void swiglu_kernel(
    const float* __restrict__ h, __half* __restrict__ g)
{
    int idx = blockIdx.x * 256 + threadIdx.x;
    int r = idx >> 12;
    int j = idx & 4095;
    const float* hr = h + (size_t)r * (2 * HIDDEN);
    float xp = hr[j];
    float gt = hr[j + HIDDEN];
    float sg = 1.0f / (1.0f + __expf(-gt));
    g[idx] = __float2half_rn(gt * sg * xp);
}

// ---------------- launch ----------------
extern "C" void kernel_launch(void* const* d_in, const int* in_sizes, int n_in,
                              void* d_out, int out_size)
{
    const float* x      = (const float*)d_in[0];
    const float* w_qkv  = (const float*)d_in[3];
    const float* b_qkv  = (const float*)d_in[4];
    const float* w_o    = (const float*)d_in[5];
    const float* b_o    = (const float*)d_in[6];
    const float* scale1 = (const float*)d_in[7];
    const float* scale2 = (const float*)d_in[8];
    const float* w1     = (const float*)d_in[9];
    const float* b1     = (const float*)d_in[10];
    const float* w2     = (const float*)d_in[11];
    const float* b2     = (const float*)d_in[12];
    float* out = (float*)d_out;

    float *qkvp, *x1, *hbuf;
    __half *xn, *att, *ffn, *wthi, *wtlo;
    cudaGetSymbolAddress((void**)&qkvp, g_qkv);
    cudaGetSymbolAddress((void**)&x1,   g_x1);
    cudaGetSymbolAddress((void**)&hbuf, g_h);
    cudaGetSymbolAddress((void**)&xn,   g_xn);
    cudaGetSymbolAddress((void**)&att,  g_att);
    cudaGetSymbolAddress((void**)&ffn,  g_ffn);
    cudaGetSymbolAddress((void**)&wthi, g_wthi);
    cudaGetSymbolAddress((void**)&wtlo, g_wtlo);

    cudaFuncSetAttribute(wmma_gemm, cudaFuncAttributeMaxDynamicSharedMemorySize, GSMEM);
    int fa_smem = 4 * 64 * FST * (int)sizeof(float);
    cudaFuncSetAttribute(flash_attn_kernel,
                         cudaFuncAttributeMaxDynamicSharedMemorySize, fa_smem);

    const size_t OFF_QKV = 0, OFF_O = 3145728, OFF_W1 = 4194304, OFF_W2 = 12582912;

    // 0) transpose + split weights (fp16 hi/lo)
    wsplit_kernel<<<dim3(3072/32, 1024/32), 256>>>(w_qkv, 1024, 3072, wthi+OFF_QKV, wtlo+OFF_QKV);
    wsplit_kernel<<<dim3(1024/32, 1024/32), 256>>>(w_o,   1024, 1024, wthi+OFF_O,   wtlo+OFF_O);
    wsplit_kernel<<<dim3(8192/32, 1024/32), 256>>>(w1,    1024, 8192, wthi+OFF_W1,  wtlo+OFF_W1);
    wsplit_kernel<<<dim3(1024/32, 4096/32), 256>>>(w2,    4096, 1024, wthi+OFF_W2,  wtlo+OFF_W2);

    // 1) xn = rmsnorm(x, scale1) -> fp16
    rmsnorm_kernel<<<ROWS, 256>>>(x, scale1, xn);
    // 2) qkv = xn @ w_qkv + b_qkv
    wmma_gemm<<<dim3(3072/128, ROWS/128), 256, GSMEM>>>(
        xn, wthi+OFF_QKV, wtlo+OFF_QKV, b_qkv, nullptr, qkvp, ROWS, 3072, 1024);
    // 3) attention -> fp16
    flash_attn_kernel<<<dim3(SEQ/64, BATCH*NHEAD), 256, fa_smem>>>(qkvp, att);
    // 4) x1 = x + att @ w_o + b_o
    wmma_gemm<<<dim3(1024/128, ROWS/128), 256, GSMEM>>>(
        att, wthi+OFF_O, wtlo+OFF_O, b_o, x, x1, ROWS, 1024, 1024);
    // 5) xn = rmsnorm(x1, scale2) -> fp16
    rmsnorm_kernel<<<ROWS, 256>>>(x1, scale2, xn);
    // 6) h = xn @ w1 + b1
    wmma_gemm<<<dim3(8192/128, ROWS/128), 256, GSMEM>>>(
        xn, wthi+OFF_W1, wtlo+OFF_W1, b1, nullptr, hbuf, ROWS, 8192, 1024);
    // 7) ffn = silu(gate) * x_proj -> fp16
    swiglu_kernel<<<ROWS * HIDDEN / 256, 256>>>(hbuf, ffn);
    // 8) out = x1 + ffn @ w2 + b2
    wmma_gemm<<<dim3(1024/128, ROWS/128), 256, GSMEM>>>(
        ffn, wthi+OFF_W2, wtlo+OFF_W2, b2, x1, out, ROWS, 1024, 4096);
}

// round 10
// speedup vs baseline: 4.0155x; 1.8706x over previous
#include <cuda_runtime.h>
#include <cuda_fp16.h>
#include <mma.h>
#include <math.h>
#include <stdint.h>

using namespace nvcuda;

#define D_MODEL 1024
#define NHEAD 16
#define HEAD_DIM 64
#define HIDDEN 4096
#define BATCH 2
#define SEQ 2048
#define ROWS (BATCH * SEQ)   // 4096

// ---------------- scratch (allocation-free: __device__ globals) ----------------
__device__ float g_qkv[(size_t)ROWS * 3 * D_MODEL];
__device__ float g_x1 [(size_t)ROWS * D_MODEL];
__device__ float g_h  [(size_t)ROWS * 2 * HIDDEN];
__device__ __half g_xn  [(size_t)ROWS * D_MODEL];
__device__ __half g_att [(size_t)ROWS * D_MODEL];
__device__ __half g_ffn [(size_t)ROWS * HIDDEN];
// transposed fp16 weights [N,K], concatenated:
//   [0)        qkvT  3072x1024
//   [3145728)  oT    1024x1024
//   [4194304)  w1T   8192x1024
//   [12582912) w2T   1024x4096
__device__ __half g_wt[16777216];

// ---------------- helpers ----------------
__device__ __forceinline__ uint32_t smem_u32(const void* p) {
    uint32_t a;
    asm("{ .reg .u64 t; cvta.to.shared.u64 t, %1; cvt.u32.u64 %0, t; }"
        : "=r"(a) : "l"(p));
    return a;
}
__device__ __forceinline__ void cp16(void* dst_smem, const void* src) {
    uint32_t d = smem_u32(dst_smem);
    asm volatile("cp.async.cg.shared.global [%0], [%1], 16;" :: "r"(d), "l"(src));
}
__device__ __forceinline__ void cp_commit() {
    asm volatile("cp.async.commit_group;" ::: "memory");
}
template<int N> __device__ __forceinline__ void cp_wait() {
    asm volatile("cp.async.wait_group %0;" :: "n"(N) : "memory");
}

// ---------------- weight transpose + fp16: W[K,N] -> Wt [N,K] ----------------
__global__ __launch_bounds__(256) void wsplit_kernel(
    const float* __restrict__ W, int K, int N, __half* __restrict__ T)
{
    __shared__ float t[32][33];
    int tx = threadIdx.x & 31, ty = threadIdx.x >> 5;  // 32x8
    int n0 = blockIdx.x * 32, k0 = blockIdx.y * 32;
    #pragma unroll
    for (int j = 0; j < 4; j++)
        t[ty + j * 8][tx] = W[(size_t)(k0 + ty + j * 8) * N + n0 + tx];
    __syncthreads();
    #pragma unroll
    for (int j = 0; j < 4; j++) {
        int n = n0 + ty + j * 8, k = k0 + tx;
        T[(size_t)n * K + k] = __float2half_rn(t[tx][ty + j * 8]);
    }
}

// ---------------- RMSNorm -> fp16 ----------------
__global__ __launch_bounds__(256) void rmsnorm_kernel(
    const float* __restrict__ x, const float* __restrict__ scale,
    __half* __restrict__ y)
{
    int row = blockIdx.x;
    const float* xr = x + (size_t)row * D_MODEL;
    int t = threadIdx.x;
    float v0 = xr[t], v1 = xr[t + 256], v2 = xr[t + 512], v3 = xr[t + 768];
    float ss = v0*v0 + v1*v1 + v2*v2 + v3*v3;
    #pragma unroll
    for (int o = 16; o; o >>= 1) ss += __shfl_xor_sync(0xffffffffu, ss, o);
    __shared__ float red[8];
    if ((t & 31) == 0) red[t >> 5] = ss;
    __syncthreads();
    float tot = 0.f;
    #pragma unroll
    for (int w = 0; w < 8; w++) tot += red[w];
    float r = rsqrtf(tot * (1.0f / D_MODEL) + 1e-8f);
    size_t base = (size_t)row * D_MODEL;
    y[base + t]       = __float2half_rn(scale[t]       * v0 * r);
    y[base + t + 256] = __float2half_rn(scale[t + 256] * v1 * r);
    y[base + t + 512] = __float2half_rn(scale[t + 512] * v2 * r);
    y[base + t + 768] = __float2half_rn(scale[t + 768] * v3 * r);
}

// ---------------- wmma fp16 GEMM: C[M,N] = A[M,K] @ Bt[N,K]^T + bias (+res) ------
// CTA 128x128, 8 warps (4x2), warp tile 32x64 = 2x4 wmma 16x16x16 frags.
// BK=32, cp.async double-buffered. Tiles: A, B; padded to 40 half/row.
#define BKP 40
#define TILE_E (128 * BKP)                 // half elems per tile (5120)
#define STG_E  (2 * TILE_E)                // elems per stage (A,B)
#define GSMEM  69632                       // epilogue 8*32*68*4 dominates (stages: 40960)

__global__ __launch_bounds__(256) void wmma_gemm(
    const __half* __restrict__ A, const __half* __restrict__ B,
    const float* __restrict__ bias, const float* __restrict__ res,
    float* __restrict__ C, int M, int N, int K)
{
    extern __shared__ __align__(128) __half sm[];
    int tid = threadIdx.x, wid = tid >> 5, lane = tid & 31;
    int bm = blockIdx.y, bn = blockIdx.x;
    int wm = wid >> 1, wn = wid & 1;

    wmma::fragment<wmma::accumulator, 16, 16, 16, float> acc[2][4];
    #pragma unroll
    for (int i = 0; i < 2; i++)
        #pragma unroll
        for (int j = 0; j < 4; j++) wmma::fill_fragment(acc[i][j], 0.f);

    const __half* gb0 = A + (size_t)bm * 128 * K;
    const __half* gb1 = B + (size_t)bn * 128 * K;

    const int S = K >> 5;
    int ld_row = tid >> 1;              // 0..127
    int ld_seg = (tid & 1) << 1;        // 0 or 2

    {
        __half* st = sm;
        size_t go = (size_t)ld_row * K + ld_seg * 8;
        uint32_t so = ld_row * BKP + ld_seg * 8;
        cp16(st + so,              gb0 + go);
        cp16(st + so + 8,          gb0 + go + 8);
        cp16(st + TILE_E + so,     gb1 + go);
        cp16(st + TILE_E + so + 8, gb1 + go + 8);
        cp_commit();
    }

    for (int s = 0; s < S; s++) {
        if (s + 1 < S) {
            __half* st = sm + ((s + 1) & 1) * STG_E;
            size_t go = (size_t)ld_row * K + ((s + 1) << 5) + ld_seg * 8;
            uint32_t so = ld_row * BKP + ld_seg * 8;
            cp16(st + so,              gb0 + go);
            cp16(st + so + 8,          gb0 + go + 8);
            cp16(st + TILE_E + so,     gb1 + go);
            cp16(st + TILE_E + so + 8, gb1 + go + 8);
            cp_commit();
            cp_wait<1>();
        } else {
            cp_wait<0>();
        }
        __syncthreads();

        __half* st = sm + (s & 1) * STG_E;
        const __half* As = st;
        const __half* Bs = st + TILE_E;

        #pragma unroll
        for (int kk = 0; kk < 32; kk += 16) {
            wmma::fragment<wmma::matrix_a, 16, 16, 16, __half, wmma::row_major> a[2];
            wmma::fragment<wmma::matrix_b, 16, 16, 16, __half, wmma::col_major> b[4];
            #pragma unroll
            for (int i = 0; i < 2; i++)
                wmma::load_matrix_sync(a[i], As + (wm * 32 + i * 16) * BKP + kk, BKP);
            #pragma unroll
            for (int j = 0; j < 4; j++)
                wmma::load_matrix_sync(b[j], Bs + (wn * 64 + j * 16) * BKP + kk, BKP);
            #pragma unroll
            for (int i = 0; i < 2; i++)
                #pragma unroll
                for (int j = 0; j < 4; j++)
                    wmma::mma_sync(acc[i][j], a[i], b[j], acc[i][j]);
        }
        __syncthreads();
    }

    // epilogue: stage accumulators through smem, fuse bias (+res)
    float* stg  = (float*)sm;
    float* wstg = stg + wid * 32 * 68;
    #pragma unroll
    for (int i = 0; i < 2; i++)
        #pragma unroll
        for (int j = 0; j < 4; j++)
            wmma::store_matrix_sync(wstg + i * 16 * 68 + j * 16, acc[i][j], 68,
                                    wmma::mem_row_major);
    __syncwarp();

    int row  = bm * 128 + wm * 32 + lane;
    int col0 = bn * 128 + wn * 64;
    float* Cr = C + (size_t)row * N + col0;
    const float* br = bias + col0;
    const float* rr = res ? res + (size_t)row * N + col0 : nullptr;
    const float* srow = wstg + lane * 68;
    #pragma unroll
    for (int c = 0; c < 16; c++) {
        float4 o = *(const float4*)(srow + c * 4);
        float4 bv = *(const float4*)(br + c * 4);
        o.x += bv.x; o.y += bv.y; o.z += bv.z; o.w += bv.w;
        if (rr) {
            float4 rv = *(const float4*)(rr + c * 4);
            o.x += rv.x; o.y += rv.y; o.z += rv.z; o.w += rv.w;
        }
        *(float4*)(Cr + c * 4) = o;
    }
}

// ---------------- Flash attention via wmma (causal + analytic ALiBi) ----------
// grid (SEQ/64, BATCH*NHEAD), 256 threads, 8 warps.
// Tiles 64x64. Warp w: row block (w>>1), col blocks (w&1)*2..+1 (16x16 frags).
#define AP 72    // half pad for Q,K,V,P rows
#define SP 68    // float pad for S,O rows
#define FA_SMEM (4*64*AP*2 + 2*64*SP*4 + 2*64*4)   // 36864+34816+512 = 72192

__global__ __launch_bounds__(256) void flash_wmma_kernel(
    const float* __restrict__ qkv, __half* __restrict__ outp)
{
    extern __shared__ __align__(128) char smraw[];
    __half* Qh = (__half*)smraw;           // 64*AP
    __half* Kh = Qh + 64 * AP;
    __half* Vh = Kh + 64 * AP;
    __half* Ph = Vh + 64 * AP;
    float*  Sf = (float*)(Ph + 64 * AP);   // 64*SP
    float*  Of = Sf + 64 * SP;             // 64*SP
    float*  mrow = Of + 64 * SP;           // 64
    float*  lrow = mrow + 64;              // 64

    int qt = blockIdx.x;
    int bh = blockIdx.y;
    int b  = bh >> 4, h = bh & 15;
    float slope = exp2f(-0.5f * (float)(h + 1));

    int tid = threadIdx.x, wid = tid >> 5;
    int rw = wid >> 1, cb0 = (wid & 1) * 2;
    int r  = tid >> 2, cg = tid & 3;       // softmax: row r, col group cg (16 cols)

    // load Q tile -> fp16
    {
        int cl = cg << 4;
        const float* src = qkv + (size_t)(b * SEQ + qt * 64 + r) * 3072 + h * 64 + cl;
        __half* dst = Qh + r * AP + cl;
        #pragma unroll
        for (int t = 0; t < 4; t++) {
            float4 v = *(const float4*)(src + t * 4);
            dst[t*4+0] = __float2half_rn(v.x); dst[t*4+1] = __float2half_rn(v.y);
            dst[t*4+2] = __float2half_rn(v.z); dst[t*4+3] = __float2half_rn(v.w);
        }
    }
    // init O, m, l
    for (int i = tid; i < 64 * SP; i += 256) Of[i] = 0.f;
    if (tid < 64) { mrow[tid] = -1e30f; lrow[tid] = 0.f; }
    __syncthreads();

    for (int kt = 0; kt <= qt; kt++) {
        // load K,V tiles -> fp16
        {
            int cl = cg << 4;
            const float* sk = qkv + (size_t)(b * SEQ + kt * 64 + r) * 3072 + 1024 + h * 64 + cl;
            const float* sv = sk + 1024;
            __half* dk = Kh + r * AP + cl;
            __half* dv = Vh + r * AP + cl;
            #pragma unroll
            for (int t = 0; t < 4; t++) {
                float4 vk = *(const float4*)(sk + t * 4);
                float4 vv = *(const float4*)(sv + t * 4);
                dk[t*4+0] = __float2half_rn(vk.x); dk[t*4+1] = __float2half_rn(vk.y);
                dk[t*4+2] = __float2half_rn(vk.z); dk[t*4+3] = __float2half_rn(vk.w);
                dv[t*4+0] = __float2half_rn(vv.x); dv[t*4+1] = __float2half_rn(vv.y);
                dv[t*4+2] = __float2half_rn(vv.z); dv[t*4+3] = __float2half_rn(vv.w);
            }
        }
        __syncthreads();

        // S = Q @ K^T (fp32 acc)
        {
            wmma::fragment<wmma::accumulator, 16, 16, 16, float> c[2];
            #pragma unroll
            for (int j = 0; j < 2; j++) wmma::fill_fragment(c[j], 0.f);
            #pragma unroll
            for (int ks = 0; ks < 4; ks++) {
                wmma::fragment<wmma::matrix_a, 16, 16, 16, __half, wmma::row_major> a;
                wmma::load_matrix_sync(a, Qh + rw * 16 * AP + ks * 16, AP);
                #pragma unroll
                for (int j = 0; j < 2; j++) {
                    wmma::fragment<wmma::matrix_b, 16, 16, 16, __half, wmma::col_major> bk;
                    wmma::load_matrix_sync(bk, Kh + (cb0 + j) * 16 * AP + ks * 16, AP);
                    wmma::mma_sync(c[j], a, bk, c[j]);
                }
            }
            #pragma unroll
            for (int j = 0; j < 2; j++)
                wmma::store_matrix_sync(Sf + rw * 16 * SP + (cb0 + j) * 16, c[j],
                                        SP, wmma::mem_row_major);
        }
        __syncthreads();

        // softmax pass (scalar, fp32) + scale O rows + P -> fp16
        {
            int iq = qt * 64 + r;
            int jb = kt * 64 + (cg << 4);
            float* srow = Sf + r * SP + (cg << 4);
            float vals[16];
            float mloc = -1e30f;
            #pragma unroll
            for (int c = 0; c < 16; c++) {
                int jj = jb + c;
                float val = srow[c] * 0.125f - slope * (float)(iq - jj);
                if (jj > iq) val = -1e30f;
                vals[c] = val;
                mloc = fmaxf(mloc, val);
            }
            mloc = fmaxf(mloc, __shfl_xor_sync(0xffffffffu, mloc, 1));
            mloc = fmaxf(mloc, __shfl_xor_sync(0xffffffffu, mloc, 2));
            float mold = mrow[r];
            float mnew = fmaxf(mold, mloc);
            float corr = __expf(mold - mnew);
            float ps = 0.f;
            __half* prow = Ph + r * AP + (cg << 4);
            #pragma unroll
            for (int c = 0; c < 16; c++) {
                float p = __expf(vals[c] - mnew);
                prow[c] = __float2half_rn(p);
                ps += p;
            }
            ps += __shfl_xor_sync(0xffffffffu, ps, 1);
            ps += __shfl_xor_sync(0xffffffffu, ps, 2);
            float* orow = Of + r * SP + (cg << 4);
            #pragma unroll
            for (int c = 0; c < 16; c++) orow[c] *= corr;
            if (cg == 0) { mrow[r] = mnew; lrow[r] = lrow[r] * corr + ps; }
        }
        __syncthreads();

        // O += P @ V (fp32 acc through smem)
        {
            wmma::fragment<wmma::accumulator, 16, 16, 16, float> oa[2];
            #pragma unroll
            for (int j = 0; j < 2; j++)
                wmma::load_matrix_sync(oa[j], Of + rw * 16 * SP + (cb0 + j) * 16,
                                       SP, wmma::mem_row_major);
            #pragma unroll
            for (int ks = 0; ks < 4; ks++) {
                wmma::fragment<wmma::matrix_a, 16, 16, 16, __half, wmma::row_major> pa;
                wmma::load_matrix_sync(pa, Ph + rw * 16 * AP + ks * 16, AP);
                #pragma unroll
                for (int j = 0; j < 2; j++) {
                    wmma::fragment<wmma::matrix_b, 16, 16, 16, __half, wmma::row_major> vb;
                    wmma::load_matrix_sync(vb, Vh + ks * 16 * AP + (cb0 + j) * 16, AP);
                    wmma::mma_sync(oa[j], pa, vb, oa[j]);
                }
            }
            #pragma unroll
            for (int j = 0; j < 2; j++)
                wmma::store_matrix_sync(Of + rw * 16 * SP + (cb0 + j) * 16, oa[j],
                                        SP, wmma::mem_row_major);
        }
        __syncthreads();
    }

    // epilogue: normalize, write fp16
    {
        float inv = 1.0f / lrow[r];
        const float* orow = Of + r * SP + (cg << 4);
        size_t off = (size_t)(b * SEQ + qt * 64 + r) * D_MODEL + h * 64 + (cg << 4);
        #pragma unroll
        for (int c = 0; c < 16; c++)
            outp[off + c] = __float2half_rn(orow[c] * inv);
    }
}

// ---------------- SwiGLU -> fp16 ----------------
__global__ __launch_bounds__(256) void swiglu_kernel(
    const float* __restrict__ h, __half* __restrict__ g)
{
    int idx = blockIdx.x * 256 + threadIdx.x;
    int r = idx >> 12;
    int j = idx & 4095;
    const float* hr = h + (size_t)r * (2 * HIDDEN);
    float xp = hr[j];
    float gt = hr[j + HIDDEN];
    float sg = 1.0f / (1.0f + __expf(-gt));
    g[idx] = __float2half_rn(gt * sg * xp);
}

// ---------------- launch ----------------
extern "C" void kernel_launch(void* const* d_in, const int* in_sizes, int n_in,
                              void* d_out, int out_size)
{
    const float* x      = (const float*)d_in[0];
    const float* w_qkv  = (const float*)d_in[3];
    const float* b_qkv  = (const float*)d_in[4];
    const float* w_o    = (const float*)d_in[5];
    const float* b_o    = (const float*)d_in[6];
    const float* scale1 = (const float*)d_in[7];
    const float* scale2 = (const float*)d_in[8];
    const float* w1     = (const float*)d_in[9];
    const float* b1     = (const float*)d_in[10];
    const float* w2     = (const float*)d_in[11];
    const float* b2     = (const float*)d_in[12];
    float* out = (float*)d_out;

    float *qkvp, *x1, *hbuf;
    __half *xn, *att, *ffn, *wt;
    cudaGetSymbolAddress((void**)&qkvp, g_qkv);
    cudaGetSymbolAddress((void**)&x1,   g_x1);
    cudaGetSymbolAddress((void**)&hbuf, g_h);
    cudaGetSymbolAddress((void**)&xn,   g_xn);
    cudaGetSymbolAddress((void**)&att,  g_att);
    cudaGetSymbolAddress((void**)&ffn,  g_ffn);
    cudaGetSymbolAddress((void**)&wt,   g_wt);

    cudaFuncSetAttribute(wmma_gemm, cudaFuncAttributeMaxDynamicSharedMemorySize, GSMEM);
    cudaFuncSetAttribute(flash_wmma_kernel,
                         cudaFuncAttributeMaxDynamicSharedMemorySize, FA_SMEM);

    const size_t OFF_QKV = 0, OFF_O = 3145728, OFF_W1 = 4194304, OFF_W2 = 12582912;

    // 0) transpose weights -> fp16
    wsplit_kernel<<<dim3(3072/32, 1024/32), 256>>>(w_qkv, 1024, 3072, wt+OFF_QKV);
    wsplit_kernel<<<dim3(1024/32, 1024/32), 256>>>(w_o,   1024, 1024, wt+OFF_O);
    wsplit_kernel<<<dim3(8192/32, 1024/32), 256>>>(w1,    1024, 8192, wt+OFF_W1);
    wsplit_kernel<<<dim3(1024/32, 4096/32), 256>>>(w2,    4096, 1024, wt+OFF_W2);

    // 1) xn = rmsnorm(x, scale1) -> fp16
    rmsnorm_kernel<<<ROWS, 256>>>(x, scale1, xn);
    // 2) qkv = xn @ w_qkv + b_qkv
    wmma_gemm<<<dim3(3072/128, ROWS/128), 256, GSMEM>>>(
        xn, wt+OFF_QKV, b_qkv, nullptr, qkvp, ROWS, 3072, 1024);
    // 3) attention (wmma) -> fp16
    flash_wmma_kernel<<<dim3(SEQ/64, BATCH*NHEAD), 256, FA_SMEM>>>(qkvp, att);
    // 4) x1 = x + att @ w_o + b_o
    wmma_gemm<<<dim3(1024/128, ROWS/128), 256, GSMEM>>>(
        att, wt+OFF_O, b_o, x, x1, ROWS, 1024, 1024);
    // 5) xn = rmsnorm(x1, scale2) -> fp16
    rmsnorm_kernel<<<ROWS, 256>>>(x1, scale2, xn);
    // 6) h = xn @ w1 + b1
    wmma_gemm<<<dim3(8192/128, ROWS/128), 256, GSMEM>>>(
        xn, wt+OFF_W1, b1, nullptr, hbuf, ROWS, 8192, 1024);
    // 7) ffn = silu(gate) * x_proj -> fp16
    swiglu_kernel<<<ROWS * HIDDEN / 256, 256>>>(hbuf, ffn);
    // 8) out = x1 + ffn @ w2 + b2
    wmma_gemm<<<dim3(1024/128, ROWS/128), 256, GSMEM>>>(
        ffn, wt+OFF_W2, b2, x1, out, ROWS, 1024, 4096);
}